// round 1
// baseline (speedup 1.0000x reference)
#include <cuda_runtime.h>
#include <cstdint>
#include <cstddef>

// Problem constants (match reference)
#define N_NODES 50000
#define N_EDGES 800000
#define D_IN    128
#define D_HID   256
#define D_OUT   128

// ---------------------------------------------------------------------------
// Device scratch (static globals — no runtime allocation allowed)
// ---------------------------------------------------------------------------
__device__ float g_deg[N_NODES];
__device__ float g_invdeg[N_NODES];
__device__ float g_agg1[(size_t)N_NODES * D_IN];    // 25.6 MB
__device__ float g_h[(size_t)N_NODES * D_HID];      // 51.2 MB
__device__ float g_agg2[(size_t)N_NODES * D_HID];   // 51.2 MB
__device__ int   g_idx64;                           // 1 if edge_index is int64

// ---------------------------------------------------------------------------
// No-return global reductions (sm_90+ vector red)
// ---------------------------------------------------------------------------
__device__ __forceinline__ void red_add_v4(float* addr, float4 v) {
    asm volatile("red.global.add.v4.f32 [%0], {%1,%2,%3,%4};"
                 :: "l"(addr), "f"(v.x), "f"(v.y), "f"(v.z), "f"(v.w)
                 : "memory");
}
__device__ __forceinline__ void red_add_f32(float* addr, float v) {
    asm volatile("red.global.add.f32 [%0], %1;"
                 :: "l"(addr), "f"(v) : "memory");
}

// ---------------------------------------------------------------------------
// Detect whether edge_index is int64 or int32.
// If the data is really int32, reading it as int64 packs two random values
// in [0, 50000) into one 64-bit word -> value >= 2^32 almost surely.
// ---------------------------------------------------------------------------
__global__ void detect_idx_kernel(const void* __restrict__ eidx) {
    if (blockIdx.x == 0 && threadIdx.x == 0) {
        const long long* p = (const long long*)eidx;
        int ok = 1;
        #pragma unroll 4
        for (int i = 0; i < 512; ++i) {
            long long v = p[i];
            if (v < 0 || v >= (long long)N_NODES) { ok = 0; break; }
        }
        g_idx64 = ok;
    }
}

// ---------------------------------------------------------------------------
// Zero-fill (float4 stores). n must be divisible by 4.
// ---------------------------------------------------------------------------
__global__ void fill0_kernel(float* __restrict__ p, size_t n4) {
    size_t i = (size_t)blockIdx.x * blockDim.x + threadIdx.x;
    size_t stride = (size_t)gridDim.x * blockDim.x;
    float4 z = make_float4(0.f, 0.f, 0.f, 0.f);
    for (; i < n4; i += stride) ((float4*)p)[i] = z;
}

// ---------------------------------------------------------------------------
// Scatter layer 1: one warp per edge. Gather x[src] (128 floats = 1 float4
// per lane) and red-add into g_agg1[dst]. Lane 0 also counts degree.
// ---------------------------------------------------------------------------
__global__ void scatter1_kernel(const float* __restrict__ x,
                                const void* __restrict__ eidx) {
    long long gtid = (long long)blockIdx.x * blockDim.x + threadIdx.x;
    long long e = gtid >> 5;
    if (e >= N_EDGES) return;
    int lane = threadIdx.x & 31;

    long long src, dst;
    if (g_idx64) {
        const long long* ep = (const long long*)eidx;
        src = ep[e];
        dst = ep[N_EDGES + e];
    } else {
        const int* ep = (const int*)eidx;
        src = ep[e];
        dst = ep[N_EDGES + e];
    }

    float4 v = ((const float4*)(x + src * D_IN))[lane];
    red_add_v4(g_agg1 + dst * D_IN + lane * 4, v);
    if (lane == 0) red_add_f32(g_deg + dst, 1.0f);
}

// ---------------------------------------------------------------------------
// Scatter layer 2: one warp per edge, 256 floats per row = 2 float4 per lane.
// ---------------------------------------------------------------------------
__global__ void scatter2_kernel(const void* __restrict__ eidx) {
    long long gtid = (long long)blockIdx.x * blockDim.x + threadIdx.x;
    long long e = gtid >> 5;
    if (e >= N_EDGES) return;
    int lane = threadIdx.x & 31;

    long long src, dst;
    if (g_idx64) {
        const long long* ep = (const long long*)eidx;
        src = ep[e];
        dst = ep[N_EDGES + e];
    } else {
        const int* ep = (const int*)eidx;
        src = ep[e];
        dst = ep[N_EDGES + e];
    }

    const float4* hr = (const float4*)(g_h + src * (size_t)D_HID);
    float4 v0 = hr[lane];
    float4 v1 = hr[lane + 32];
    float* base = g_agg2 + dst * (size_t)D_HID;
    red_add_v4(base + lane * 4, v0);
    red_add_v4(base + 128 + lane * 4, v1);
}

// ---------------------------------------------------------------------------
// inv_deg = 1 / max(deg, 1)
// ---------------------------------------------------------------------------
__global__ void invdeg_kernel() {
    int i = blockIdx.x * blockDim.x + threadIdx.x;
    if (i < N_NODES) g_invdeg[i] = 1.0f / fmaxf(g_deg[i], 1.0f);
}

// ---------------------------------------------------------------------------
// Fused SAGE GEMM:  C[n, j] = bias[j]
//                             + sum_k X[n,k]   * Wr[j,k]
//                             + sum_k AGGs[n,k]* Wl[j,k],  AGGs = AGG * invdeg
// Treated as one GEMM with K = 2*D: first D k's from (X, Wr), last D from
// (AGG*invdeg, Wl). BK=16 divides D, so each K-tile is uniformly one side.
// Tiling: BM=128, BN=64, BK=16, 256 threads, 8x4 per-thread accumulator.
// ---------------------------------------------------------------------------
#define BM 128
#define BN 64
#define BK 16

template<int D, int NCOLS>
__global__ __launch_bounds__(256)
void sage_gemm_kernel(const float* __restrict__ X,
                      const float* __restrict__ AGG,
                      const float* __restrict__ Wr,
                      const float* __restrict__ Wl,
                      const float* __restrict__ bias,
                      float* __restrict__ C,
                      int M) {
    __shared__ float As[BK][BM];
    __shared__ float Bs[BK][BN];

    const int tid = threadIdx.x;
    const int m0 = blockIdx.x * BM;
    const int n0 = blockIdx.y * BN;

    // loader coordinates
    const int ar = tid >> 2;          // 0..63 (row within half-tile)
    const int ak = (tid & 3) * 4;     // 0,4,8,12
    const int br = tid >> 2;          // 0..63 (output col within tile)
    const int bk = (tid & 3) * 4;

    // compute coordinates
    const int ty = tid >> 4;          // 0..15 -> rows ty*8..ty*8+7
    const int tx = tid & 15;          // 0..15 -> cols tx*4..tx*4+3

    float acc[8][4];
    #pragma unroll
    for (int i = 0; i < 8; ++i)
        #pragma unroll
        for (int j = 0; j < 4; ++j) acc[i][j] = 0.f;

    constexpr int KTILES = (2 * D) / BK;

    #pragma unroll 1
    for (int kt = 0; kt < KTILES; ++kt) {
        const int kbase = kt * BK;
        const bool aggside = (kbase >= D);

        // ---- load A tile (128 rows x 16 k), 2 float4 per thread ----
        #pragma unroll
        for (int p = 0; p < 2; ++p) {
            const int row = ar + p * 64;
            const int node = m0 + row;
            float4 v = make_float4(0.f, 0.f, 0.f, 0.f);
            if (node < M) {
                if (!aggside) {
                    v = *(const float4*)(X + (size_t)node * D + kbase + ak);
                } else {
                    v = *(const float4*)(AGG + (size_t)node * D + (kbase - D) + ak);
                    const float s = g_invdeg[node];
                    v.x *= s; v.y *= s; v.z *= s; v.w *= s;
                }
            }
            As[ak + 0][row] = v.x;
            As[ak + 1][row] = v.y;
            As[ak + 2][row] = v.z;
            As[ak + 3][row] = v.w;
        }

        // ---- load B tile (64 cols x 16 k), 1 float4 per thread ----
        {
            const int j = n0 + br;
            const float* W = aggside ? Wl : Wr;
            const int kk = (aggside ? (kbase - D) : kbase) + bk;
            float4 v = *(const float4*)(W + (size_t)j * D + kk);
            Bs[bk + 0][br] = v.x;
            Bs[bk + 1][br] = v.y;
            Bs[bk + 2][br] = v.z;
            Bs[bk + 3][br] = v.w;
        }

        __syncthreads();

        // ---- FMA on the tile ----
        #pragma unroll
        for (int k = 0; k < BK; ++k) {
            float a[8], b[4];
            #pragma unroll
            for (int i = 0; i < 8; ++i) a[i] = As[k][ty * 8 + i];
            float4 bv = *(const float4*)&Bs[k][tx * 4];
            b[0] = bv.x; b[1] = bv.y; b[2] = bv.z; b[3] = bv.w;
            #pragma unroll
            for (int i = 0; i < 8; ++i)
                #pragma unroll
                for (int j = 0; j < 4; ++j) acc[i][j] += a[i] * b[j];
        }

        __syncthreads();
    }

    // ---- epilogue: += bias, write C ----
    const int colbase = n0 + tx * 4;
    const float4 bb = *(const float4*)(bias + colbase);
    #pragma unroll
    for (int i = 0; i < 8; ++i) {
        const int node = m0 + ty * 8 + i;
        if (node < M) {
            float4 o;
            o.x = acc[i][0] + bb.x;
            o.y = acc[i][1] + bb.y;
            o.z = acc[i][2] + bb.z;
            o.w = acc[i][3] + bb.w;
            *(float4*)(C + (size_t)node * NCOLS + colbase) = o;
        }
    }
}

// ---------------------------------------------------------------------------
// Launch
// ---------------------------------------------------------------------------
extern "C" void kernel_launch(void* const* d_in, const int* in_sizes, int n_in,
                              void* d_out, int out_size) {
    const float* x    = (const float*)d_in[0];
    const void*  eidx = d_in[1];
    const float* W_l1 = (const float*)d_in[2];
    const float* b_l1 = (const float*)d_in[3];
    const float* W_r1 = (const float*)d_in[4];
    const float* W_l2 = (const float*)d_in[5];
    const float* b_l2 = (const float*)d_in[6];
    const float* W_r2 = (const float*)d_in[7];
    float* out = (float*)d_out;

    // resolve device-global addresses (no allocation)
    float *p_deg, *p_agg1, *p_agg2, *p_h;
    cudaGetSymbolAddress((void**)&p_deg,  g_deg);
    cudaGetSymbolAddress((void**)&p_agg1, g_agg1);
    cudaGetSymbolAddress((void**)&p_agg2, g_agg2);
    cudaGetSymbolAddress((void**)&p_h,    g_h);
    (void)p_h;

    // 0) detect index dtype
    detect_idx_kernel<<<1, 32>>>(eidx);

    // 1) zero accumulators
    {
        size_t n4;
        n4 = (size_t)N_NODES / 4;
        fill0_kernel<<<(unsigned)((n4 + 255) / 256), 256>>>(p_deg, n4);
        n4 = (size_t)N_NODES * D_IN / 4;
        fill0_kernel<<<(unsigned)((n4 + 255) / 256), 256>>>(p_agg1, n4);
        n4 = (size_t)N_NODES * D_HID / 4;
        fill0_kernel<<<(unsigned)((n4 + 255) / 256), 256>>>(p_agg2, n4);
    }

    // 2) scatter layer 1 (+ degree count)
    {
        long long threads = (long long)N_EDGES * 32;
        unsigned blocks = (unsigned)((threads + 255) / 256);
        scatter1_kernel<<<blocks, 256>>>(x, eidx);
    }

    // 3) inverse degree
    invdeg_kernel<<<(N_NODES + 255) / 256, 256>>>();

    // 4) GEMM layer 1 -> h  (M=50000, N=256, K=256)
    {
        dim3 grid((N_NODES + BM - 1) / BM, D_HID / BN);
        sage_gemm_kernel<D_IN, D_HID><<<grid, 256>>>(
            x, p_agg1, W_r1, W_l1, b_l1, p_h, N_NODES);
    }

    // 5) scatter layer 2
    {
        long long threads = (long long)N_EDGES * 32;
        unsigned blocks = (unsigned)((threads + 255) / 256);
        scatter2_kernel<<<blocks, 256>>>(eidx);
    }

    // 6) GEMM layer 2 -> out (M=50000, N=128, K=512)
    {
        dim3 grid((N_NODES + BM - 1) / BM, D_OUT / BN);
        sage_gemm_kernel<D_HID, D_OUT><<<grid, 256>>>(
            p_h, p_agg2, W_r2, W_l2, b_l2, out, N_NODES);
    }
}

// round 2
// speedup vs baseline: 1.4947x; 1.4947x over previous
#include <cuda_runtime.h>
#include <cstdint>
#include <cstddef>

// Problem constants (match reference)
#define N_NODES 50000
#define N_EDGES 800000
#define D_IN    128
#define D_HID   256
#define D_OUT   128

// ---------------------------------------------------------------------------
// Algebraic reformulation (mean_agg is linear, no activation between layers):
//   m1 = mean_agg(x)                        [N,128]
//   A2 = mean_agg(m1)                       [N,128]
//   out = A2 @ U1^T + m1 @ U2^T + x @ U3^T + c + 1{deg>0} * d
// with U1 = Wl2@Wl1, U2 = Wl2@Wr1 + Wr2@Wl1, U3 = Wr2@Wr1 (all [128,128]),
//      c = b2 + Wr2@b1, d = Wl2@b1.
// So: two 128-wide scatter-mean passes + tiny weight products + ONE GEMM
// with M=50000, N=128, K=384.
// ---------------------------------------------------------------------------

// Device scratch (static globals — no runtime allocation allowed)
__device__ float g_deg[N_NODES];
__device__ float g_invdeg[N_NODES];
__device__ float g_agg1[(size_t)N_NODES * 128];   // raw sums of x  (25.6 MB)
__device__ float g_agg2[(size_t)N_NODES * 128];   // raw sums of m1 (25.6 MB)
__device__ float g_U[128 * 384];                  // packed [U1 | U2 | U3] per out-row
__device__ float g_c[128];
__device__ float g_d[128];
__device__ int   g_idx64;                         // 1 if edge_index is int64

// ---------------------------------------------------------------------------
// No-return global reductions
// ---------------------------------------------------------------------------
__device__ __forceinline__ void red_add_v4(float* addr, float4 v) {
    asm volatile("red.global.add.v4.f32 [%0], {%1,%2,%3,%4};"
                 :: "l"(addr), "f"(v.x), "f"(v.y), "f"(v.z), "f"(v.w)
                 : "memory");
}
__device__ __forceinline__ void red_add_f32(float* addr, float v) {
    asm volatile("red.global.add.f32 [%0], %1;"
                 :: "l"(addr), "f"(v) : "memory");
}

// ---------------------------------------------------------------------------
// Detect whether edge_index is int64 or int32 (int32 data read as int64 packs
// two values in [0,50000) into one word -> >= 2^32 almost surely).
// ---------------------------------------------------------------------------
__global__ void detect_idx_kernel(const void* __restrict__ eidx) {
    const long long* p = (const long long*)eidx;
    int lane = threadIdx.x;
    int ok = 1;
    #pragma unroll
    for (int i = 0; i < 16; ++i) {
        long long v = p[lane * 16 + i];
        ok &= (v >= 0 && v < (long long)N_NODES);
    }
    unsigned m = __ballot_sync(0xffffffffu, ok);
    if (lane == 0) g_idx64 = (m == 0xffffffffu) ? 1 : 0;
}

// ---------------------------------------------------------------------------
// Zero-fill (float4 stores)
// ---------------------------------------------------------------------------
__global__ void fill0_kernel(float* __restrict__ p, size_t n4) {
    size_t i = (size_t)blockIdx.x * blockDim.x + threadIdx.x;
    size_t stride = (size_t)gridDim.x * blockDim.x;
    float4 z = make_float4(0.f, 0.f, 0.f, 0.f);
    for (; i < n4; i += stride) ((float4*)p)[i] = z;
}

// ---------------------------------------------------------------------------
// Scatter 1: one warp per edge. agg1[dst] += x[src] (128 floats = 1 f4/lane).
// Lane 0 counts degree.
// ---------------------------------------------------------------------------
__global__ void scatter1_kernel(const float* __restrict__ x,
                                const void* __restrict__ eidx) {
    long long gtid = (long long)blockIdx.x * blockDim.x + threadIdx.x;
    long long e = gtid >> 5;
    if (e >= N_EDGES) return;
    int lane = threadIdx.x & 31;

    long long src, dst;
    if (g_idx64) {
        const long long* ep = (const long long*)eidx;
        src = ep[e];
        dst = ep[N_EDGES + e];
    } else {
        const int* ep = (const int*)eidx;
        src = ep[e];
        dst = ep[N_EDGES + e];
    }

    float4 v = ((const float4*)(x + src * 128))[lane];
    red_add_v4(g_agg1 + dst * 128 + lane * 4, v);
    if (lane == 0) red_add_f32(g_deg + dst, 1.0f);
}

// ---------------------------------------------------------------------------
// inv_deg = 1 / max(deg, 1)
// ---------------------------------------------------------------------------
__global__ void invdeg_kernel() {
    int i = blockIdx.x * blockDim.x + threadIdx.x;
    if (i < N_NODES) g_invdeg[i] = 1.0f / fmaxf(g_deg[i], 1.0f);
}

// ---------------------------------------------------------------------------
// Scatter 2: agg2[dst] += agg1[src] * invdeg[src]   (i.e. += m1[src])
// ---------------------------------------------------------------------------
__global__ void scatter2_kernel(const void* __restrict__ eidx) {
    long long gtid = (long long)blockIdx.x * blockDim.x + threadIdx.x;
    long long e = gtid >> 5;
    if (e >= N_EDGES) return;
    int lane = threadIdx.x & 31;

    long long src, dst;
    if (g_idx64) {
        const long long* ep = (const long long*)eidx;
        src = ep[e];
        dst = ep[N_EDGES + e];
    } else {
        const int* ep = (const int*)eidx;
        src = ep[e];
        dst = ep[N_EDGES + e];
    }

    const float s = g_invdeg[src];
    float4 v = ((const float4*)(g_agg1 + src * 128))[lane];
    v.x *= s; v.y *= s; v.z *= s; v.w *= s;
    red_add_v4(g_agg2 + dst * 128 + lane * 4, v);
}

// ---------------------------------------------------------------------------
// Weight products: g_U[a][0:128]=Wl2@Wl1, [128:256]=Wl2@Wr1+Wr2@Wl1,
//                  [256:384]=Wr2@Wr1.  K = 256.
// ---------------------------------------------------------------------------
__global__ void weightU_kernel(const float* __restrict__ Wl1,
                               const float* __restrict__ Wr1,
                               const float* __restrict__ Wl2,
                               const float* __restrict__ Wr2) {
    int idx = blockIdx.x * blockDim.x + threadIdx.x;
    if (idx >= 128 * 384) return;
    int a = idx / 384;
    int bcol = idx - a * 384;
    int seg = bcol >> 7;
    int b = bcol & 127;
    float s = 0.f;
    if (seg == 0) {
        #pragma unroll 4
        for (int k = 0; k < 256; ++k) s += Wl2[a * 256 + k] * Wl1[k * 128 + b];
    } else if (seg == 1) {
        #pragma unroll 4
        for (int k = 0; k < 256; ++k)
            s += Wl2[a * 256 + k] * Wr1[k * 128 + b]
               + Wr2[a * 256 + k] * Wl1[k * 128 + b];
    } else {
        #pragma unroll 4
        for (int k = 0; k < 256; ++k) s += Wr2[a * 256 + k] * Wr1[k * 128 + b];
    }
    g_U[idx] = s;
}

__global__ void weightcd_kernel(const float* __restrict__ b1,
                                const float* __restrict__ b2,
                                const float* __restrict__ Wl2,
                                const float* __restrict__ Wr2) {
    int a = threadIdx.x;
    if (a < 128) {
        float c = 0.f, d = 0.f;
        #pragma unroll 4
        for (int k = 0; k < 256; ++k) {
            c += Wr2[a * 256 + k] * b1[k];
            d += Wl2[a * 256 + k] * b1[k];
        }
        g_c[a] = b2[a] + c;
        g_d[a] = d;
    }
}

// ---------------------------------------------------------------------------
// Final fused GEMM: out[M,128] = A @ U^T + c + flag*d
// A[M, 384] is virtual: k in [0,128)  -> agg2 * invdeg   (= A2)
//                       k in [128,256)-> agg1 * invdeg   (= m1)
//                       k in [256,384)-> x
// BM=128, BN=128, BK=16, 256 threads, 8x8 per-thread, double-buffered smem.
// ---------------------------------------------------------------------------
#define BM 128
#define BN 128
#define BK 16
#define KTILES 24   // 384 / 16

__global__ __launch_bounds__(256)
void final_gemm_kernel(const float* __restrict__ x,
                       float* __restrict__ out,
                       int M) {
    __shared__ float As[2][BK][BM];
    __shared__ float Bs[2][BK][BN];

    const int tid = threadIdx.x;
    const int m0 = blockIdx.x * BM;

    const int lr = tid >> 2;          // 0..63
    const int lk = (tid & 3) * 4;     // 0,4,8,12

    const int ty = tid >> 4;          // 0..15
    const int tx = tid & 15;          // 0..15

    float acc[8][8];
    #pragma unroll
    for (int i = 0; i < 8; ++i)
        #pragma unroll
        for (int j = 0; j < 8; ++j) acc[i][j] = 0.f;

    // --- tile loaders (to registers) ---
    auto fetchA = [&](int kt, int p) -> float4 {
        const int node = m0 + lr + p * 64;
        float4 v = make_float4(0.f, 0.f, 0.f, 0.f);
        if (node < M) {
            const int kbase = kt * BK + lk;
            const int seg = kbase >> 7;
            const int kk = kbase & 127;
            if (seg == 0) {
                v = *(const float4*)(g_agg2 + (size_t)node * 128 + kk);
                const float s = g_invdeg[node];
                v.x *= s; v.y *= s; v.z *= s; v.w *= s;
            } else if (seg == 1) {
                v = *(const float4*)(g_agg1 + (size_t)node * 128 + kk);
                const float s = g_invdeg[node];
                v.x *= s; v.y *= s; v.z *= s; v.w *= s;
            } else {
                v = *(const float4*)(x + (size_t)node * 128 + kk);
            }
        }
        return v;
    };
    auto fetchB = [&](int kt, int p) -> float4 {
        const int j = lr + p * 64;
        return *(const float4*)(g_U + (size_t)j * 384 + kt * BK + lk);
    };
    auto stashA = [&](int b, int p, float4 v) {
        const int row = lr + p * 64;
        As[b][lk + 0][row] = v.x;
        As[b][lk + 1][row] = v.y;
        As[b][lk + 2][row] = v.z;
        As[b][lk + 3][row] = v.w;
    };
    auto stashB = [&](int b, int p, float4 v) {
        const int j = lr + p * 64;
        Bs[b][lk + 0][j] = v.x;
        Bs[b][lk + 1][j] = v.y;
        Bs[b][lk + 2][j] = v.z;
        Bs[b][lk + 3][j] = v.w;
    };

    // preload tile 0
    stashA(0, 0, fetchA(0, 0));
    stashA(0, 1, fetchA(0, 1));
    stashB(0, 0, fetchB(0, 0));
    stashB(0, 1, fetchB(0, 1));
    __syncthreads();

    int buf = 0;
    #pragma unroll 1
    for (int kt = 0; kt < KTILES; ++kt) {
        float4 na0, na1, nb0, nb1;
        const bool more = (kt + 1 < KTILES);
        if (more) {
            na0 = fetchA(kt + 1, 0);
            na1 = fetchA(kt + 1, 1);
            nb0 = fetchB(kt + 1, 0);
            nb1 = fetchB(kt + 1, 1);
        }

        // compute on current buffer
        #pragma unroll
        for (int k = 0; k < BK; ++k) {
            float4 a0 = *(const float4*)&As[buf][k][ty * 8];
            float4 a1 = *(const float4*)&As[buf][k][ty * 8 + 4];
            float4 b0 = *(const float4*)&Bs[buf][k][tx * 8];
            float4 b1 = *(const float4*)&Bs[buf][k][tx * 8 + 4];
            float a[8] = {a0.x, a0.y, a0.z, a0.w, a1.x, a1.y, a1.z, a1.w};
            float b[8] = {b0.x, b0.y, b0.z, b0.w, b1.x, b1.y, b1.z, b1.w};
            #pragma unroll
            for (int i = 0; i < 8; ++i)
                #pragma unroll
                for (int j = 0; j < 8; ++j) acc[i][j] += a[i] * b[j];
        }

        if (more) {
            stashA(buf ^ 1, 0, na0);
            stashA(buf ^ 1, 1, na1);
            stashB(buf ^ 1, 0, nb0);
            stashB(buf ^ 1, 1, nb1);
            __syncthreads();
            buf ^= 1;
        }
    }

    // epilogue: + c + 1{deg>0} * d
    const int cb = tx * 8;
    float4 c0 = *(const float4*)&g_c[cb];
    float4 c1 = *(const float4*)&g_c[cb + 4];
    float4 d0 = *(const float4*)&g_d[cb];
    float4 d1 = *(const float4*)&g_d[cb + 4];

    #pragma unroll
    for (int i = 0; i < 8; ++i) {
        const int node = m0 + ty * 8 + i;
        if (node < M) {
            const float f = (g_deg[node] > 0.f) ? 1.f : 0.f;
            float4 o0, o1;
            o0.x = acc[i][0] + c0.x + f * d0.x;
            o0.y = acc[i][1] + c0.y + f * d0.y;
            o0.z = acc[i][2] + c0.z + f * d0.z;
            o0.w = acc[i][3] + c0.w + f * d0.w;
            o1.x = acc[i][4] + c1.x + f * d1.x;
            o1.y = acc[i][5] + c1.y + f * d1.y;
            o1.z = acc[i][6] + c1.z + f * d1.z;
            o1.w = acc[i][7] + c1.w + f * d1.w;
            float* dst = out + (size_t)node * 128 + cb;
            *(float4*)dst = o0;
            *(float4*)(dst + 4) = o1;
        }
    }
}

// ---------------------------------------------------------------------------
// Launch
// ---------------------------------------------------------------------------
extern "C" void kernel_launch(void* const* d_in, const int* in_sizes, int n_in,
                              void* d_out, int out_size) {
    const float* x    = (const float*)d_in[0];
    const void*  eidx = d_in[1];
    const float* W_l1 = (const float*)d_in[2];
    const float* b_l1 = (const float*)d_in[3];
    const float* W_r1 = (const float*)d_in[4];
    const float* W_l2 = (const float*)d_in[5];
    const float* b_l2 = (const float*)d_in[6];
    const float* W_r2 = (const float*)d_in[7];
    float* out = (float*)d_out;

    float *p_deg, *p_agg1, *p_agg2;
    cudaGetSymbolAddress((void**)&p_deg,  g_deg);
    cudaGetSymbolAddress((void**)&p_agg1, g_agg1);
    cudaGetSymbolAddress((void**)&p_agg2, g_agg2);

    // 0) detect index dtype
    detect_idx_kernel<<<1, 32>>>(eidx);

    // 1) zero accumulators
    {
        size_t n4;
        n4 = (size_t)N_NODES / 4;
        fill0_kernel<<<(unsigned)((n4 + 255) / 256), 256>>>(p_deg, n4);
        n4 = (size_t)N_NODES * 128 / 4;
        fill0_kernel<<<(unsigned)((n4 + 255) / 256), 256>>>(p_agg1, n4);
        fill0_kernel<<<(unsigned)((n4 + 255) / 256), 256>>>(p_agg2, n4);
    }

    // 2) weight pre-products (independent of scatters)
    weightU_kernel<<<(128 * 384 + 255) / 256, 256>>>(W_l1, W_r1, W_l2, W_r2);
    weightcd_kernel<<<1, 128>>>(b_l1, b_l2, W_l2, W_r2);

    // 3) scatter layer 1 (+ degree count)
    {
        long long threads = (long long)N_EDGES * 32;
        unsigned blocks = (unsigned)((threads + 255) / 256);
        scatter1_kernel<<<blocks, 256>>>(x, eidx);
    }

    // 4) inverse degree
    invdeg_kernel<<<(N_NODES + 255) / 256, 256>>>();

    // 5) scatter layer 2 (mean of m1)
    {
        long long threads = (long long)N_EDGES * 32;
        unsigned blocks = (unsigned)((threads + 255) / 256);
        scatter2_kernel<<<blocks, 256>>>(eidx);
    }

    // 6) single fused GEMM -> out
    {
        dim3 grid((N_NODES + BM - 1) / BM, 1);
        final_gemm_kernel<<<grid, 256>>>(x, out, N_NODES);
    }
}

// round 4
// speedup vs baseline: 1.6239x; 1.0864x over previous
#include <cuda_runtime.h>
#include <cuda_bf16.h>
#include <cstdint>
#include <cstddef>

// Problem constants (match reference)
#define N_NODES 50000
#define N_EDGES 800000
#define D_IN    128
#define D_HID   256
#define D_OUT   128

// ---------------------------------------------------------------------------
// Algebraic reformulation (mean_agg linear, no inter-layer activation):
//   m1 = mean_agg(x); A2 = mean_agg(m1)
//   out = A2 @ U1^T + m1 @ U2^T + x @ U3^T + c + 1{deg>0} * d
//   U1 = Wl2@Wl1, U2 = Wl2@Wr1 + Wr2@Wl1, U3 = Wr2@Wr1, c = b2+Wr2@b1, d = Wl2@b1
// Final GEMM (M=50000, N=128, K=384) runs on tensor cores via
// mma.sync.m16n8k16 bf16 with fp32->bf16 hi/lo split (3-term) — base-target
// legal on sm_103 (tcgen05 is not available through this toolchain).
// ---------------------------------------------------------------------------

// Device scratch
__device__ float g_deg[N_NODES];
__device__ float g_invdeg[N_NODES];
__device__ float g_agg1[(size_t)N_NODES * 128];
__device__ float g_agg2[(size_t)N_NODES * 128];
__device__ __nv_bfloat16 g_Uhi[128 * 384];
__device__ __nv_bfloat16 g_Ulo[128 * 384];
__device__ float g_c[128];
__device__ float g_d[128];
__device__ int   g_idx64;

// ---------------------------------------------------------------------------
// PTX helpers
// ---------------------------------------------------------------------------
__device__ __forceinline__ void red_add_v4(float* addr, float4 v) {
    asm volatile("red.global.add.v4.f32 [%0], {%1,%2,%3,%4};"
                 :: "l"(addr), "f"(v.x), "f"(v.y), "f"(v.z), "f"(v.w)
                 : "memory");
}
__device__ __forceinline__ void red_add_f32(float* addr, float v) {
    asm volatile("red.global.add.f32 [%0], %1;"
                 :: "l"(addr), "f"(v) : "memory");
}

// D += A * B  (m16n8k16, row.col, bf16 in, fp32 acc)
__device__ __forceinline__ void mma16816(float* d, const uint32_t* a, const uint32_t* b) {
    asm volatile(
        "mma.sync.aligned.m16n8k16.row.col.f32.bf16.bf16.f32 "
        "{%0,%1,%2,%3}, {%4,%5,%6,%7}, {%8,%9}, {%0,%1,%2,%3};"
        : "+f"(d[0]), "+f"(d[1]), "+f"(d[2]), "+f"(d[3])
        : "r"(a[0]), "r"(a[1]), "r"(a[2]), "r"(a[3]), "r"(b[0]), "r"(b[1]));
}

// split float2 -> packed bf16x2 hi and lo
__device__ __forceinline__ void split2(float2 v, uint32_t& hi, uint32_t& lo) {
    __nv_bfloat162 h = __float22bfloat162_rn(v);
    float2 hv = __bfloat1622float2(h);
    __nv_bfloat162 l = __float22bfloat162_rn(make_float2(v.x - hv.x, v.y - hv.y));
    hi = *reinterpret_cast<uint32_t*>(&h);
    lo = *reinterpret_cast<uint32_t*>(&l);
}

// ---------------------------------------------------------------------------
// Detect whether edge_index is int64 or int32
// ---------------------------------------------------------------------------
__global__ void detect_idx_kernel(const void* __restrict__ eidx) {
    const long long* p = (const long long*)eidx;
    int lane = threadIdx.x;
    int ok = 1;
    #pragma unroll
    for (int i = 0; i < 16; ++i) {
        long long v = p[lane * 16 + i];
        ok &= (v >= 0 && v < (long long)N_NODES);
    }
    unsigned m = __ballot_sync(0xffffffffu, ok);
    if (lane == 0) g_idx64 = (m == 0xffffffffu) ? 1 : 0;
}

__global__ void fill0_kernel(float* __restrict__ p, size_t n4) {
    size_t i = (size_t)blockIdx.x * blockDim.x + threadIdx.x;
    size_t stride = (size_t)gridDim.x * blockDim.x;
    float4 z = make_float4(0.f, 0.f, 0.f, 0.f);
    for (; i < n4; i += stride) ((float4*)p)[i] = z;
}

// ---------------------------------------------------------------------------
// Scatters
// ---------------------------------------------------------------------------
__global__ void scatter1_kernel(const float* __restrict__ x,
                                const void* __restrict__ eidx) {
    long long gtid = (long long)blockIdx.x * blockDim.x + threadIdx.x;
    long long e = gtid >> 5;
    if (e >= N_EDGES) return;
    int lane = threadIdx.x & 31;

    long long src, dst;
    if (g_idx64) {
        const long long* ep = (const long long*)eidx;
        src = ep[e]; dst = ep[N_EDGES + e];
    } else {
        const int* ep = (const int*)eidx;
        src = ep[e]; dst = ep[N_EDGES + e];
    }

    float4 v = ((const float4*)(x + src * 128))[lane];
    red_add_v4(g_agg1 + dst * 128 + lane * 4, v);
    if (lane == 0) red_add_f32(g_deg + dst, 1.0f);
}

__global__ void invdeg_kernel() {
    int i = blockIdx.x * blockDim.x + threadIdx.x;
    if (i < N_NODES) g_invdeg[i] = 1.0f / fmaxf(g_deg[i], 1.0f);
}

__global__ void scatter2_kernel(const void* __restrict__ eidx) {
    long long gtid = (long long)blockIdx.x * blockDim.x + threadIdx.x;
    long long e = gtid >> 5;
    if (e >= N_EDGES) return;
    int lane = threadIdx.x & 31;

    long long src, dst;
    if (g_idx64) {
        const long long* ep = (const long long*)eidx;
        src = ep[e]; dst = ep[N_EDGES + e];
    } else {
        const int* ep = (const int*)eidx;
        src = ep[e]; dst = ep[N_EDGES + e];
    }

    const float s = g_invdeg[src];
    float4 v = ((const float4*)(g_agg1 + src * 128))[lane];
    v.x *= s; v.y *= s; v.z *= s; v.w *= s;
    red_add_v4(g_agg2 + dst * 128 + lane * 4, v);
}

// ---------------------------------------------------------------------------
// Weight pre-products (fp32 compute, bf16 hi/lo output)
// ---------------------------------------------------------------------------
__global__ void weightU_kernel(const float* __restrict__ Wl1,
                               const float* __restrict__ Wr1,
                               const float* __restrict__ Wl2,
                               const float* __restrict__ Wr2) {
    int idx = blockIdx.x * blockDim.x + threadIdx.x;
    if (idx >= 128 * 384) return;
    int a = idx / 384;
    int bcol = idx - a * 384;
    int seg = bcol >> 7;
    int b = bcol & 127;
    float s = 0.f;
    if (seg == 0) {
        #pragma unroll 4
        for (int k = 0; k < 256; ++k) s += Wl2[a * 256 + k] * Wl1[k * 128 + b];
    } else if (seg == 1) {
        #pragma unroll 4
        for (int k = 0; k < 256; ++k)
            s += Wl2[a * 256 + k] * Wr1[k * 128 + b]
               + Wr2[a * 256 + k] * Wl1[k * 128 + b];
    } else {
        #pragma unroll 4
        for (int k = 0; k < 256; ++k) s += Wr2[a * 256 + k] * Wr1[k * 128 + b];
    }
    __nv_bfloat16 hi = __float2bfloat16(s);
    __nv_bfloat16 lo = __float2bfloat16(s - __bfloat162float(hi));
    g_Uhi[idx] = hi;
    g_Ulo[idx] = lo;
}

__global__ void weightcd_kernel(const float* __restrict__ b1,
                                const float* __restrict__ b2,
                                const float* __restrict__ Wl2,
                                const float* __restrict__ Wr2) {
    int a = threadIdx.x;
    if (a < 128) {
        float c = 0.f, d = 0.f;
        #pragma unroll 4
        for (int k = 0; k < 256; ++k) {
            c += Wr2[a * 256 + k] * b1[k];
            d += Wl2[a * 256 + k] * b1[k];
        }
        g_c[a] = b2[a] + c;
        g_d[a] = d;
    }
}

// ---------------------------------------------------------------------------
// Tensor-core GEMM via mma.sync: out[M,128] = A_v[M,384] @ U^T + c + f*d
// A_v: k 0-127 -> agg2*invdeg, 128-255 -> agg1*invdeg, 256-383 -> x.
// CTA: 128x128 tile, 8 warps in 4x2 (M x N); warp: 32x64 = 2 x 8 fragments
// of m16n8k16. A loaded from global fp32 and hi/lo-split in registers;
// B from precomputed g_Uhi/g_Ulo (L1-resident).
// ---------------------------------------------------------------------------
__global__ __launch_bounds__(256)
void mma_gemm_kernel(const float* __restrict__ x, float* __restrict__ out, int M) {
    const int tid  = threadIdx.x;
    const int wid  = tid >> 5;
    const int lane = tid & 31;
    const int g    = lane >> 2;       // group (0..7)
    const int tq   = lane & 3;        // thread-in-quad
    const int m0   = blockIdx.x * 128;
    const int moff = (wid >> 1) * 32; // 0,32,64,96
    const int noff = (wid & 1) * 64;  // 0,64

    // 4 distinct A rows for this thread: mi*2 + h -> m0+moff+mi*16+h*8+g
    int   rows[4];
    bool  rowok[4];
    float invd[4];
    float flag[4];
    #pragma unroll
    for (int r = 0; r < 4; ++r) {
        const int mi = r >> 1, h = r & 1;
        rows[r]  = m0 + moff + mi * 16 + h * 8 + g;
        rowok[r] = rows[r] < M;
        invd[r]  = rowok[r] ? g_invdeg[rows[r]] : 0.f;
        flag[r]  = (rowok[r] && g_deg[rows[r]] > 0.f) ? 1.f : 0.f;
    }

    float acc[2][8][4];
    #pragma unroll
    for (int mi = 0; mi < 2; ++mi)
        #pragma unroll
        for (int ni = 0; ni < 8; ++ni)
            #pragma unroll
            for (int q = 0; q < 4; ++q) acc[mi][ni][q] = 0.f;

    // K loop: 3 segments x 8 k16-steps
    #pragma unroll 1
    for (int s = 0; s < 3; ++s) {
        const float* Asrc = (s == 0) ? g_agg2 : ((s == 1) ? g_agg1 : x);
        const bool scale = (s < 2);
        const int kseg = s * 128;

        #pragma unroll 1
        for (int kt = 0; kt < 8; ++kt) {
            const int kk = kt * 16;            // within segment
            const int kb = kseg + kk;          // within U rows

            // ---- B fragments (hi/lo) ----
            uint32_t bh[8][2], bl[8][2];
            #pragma unroll
            for (int ni = 0; ni < 8; ++ni) {
                const int n = noff + ni * 8 + g;
                const size_t base = (size_t)n * 384 + kb + tq * 2;
                bh[ni][0] = *(const uint32_t*)(g_Uhi + base);
                bh[ni][1] = *(const uint32_t*)(g_Uhi + base + 8);
                bl[ni][0] = *(const uint32_t*)(g_Ulo + base);
                bl[ni][1] = *(const uint32_t*)(g_Ulo + base + 8);
            }

            // ---- A fragments (load fp32, split hi/lo) ----
            uint32_t ah[2][4], al[2][4];
            #pragma unroll
            for (int mi = 0; mi < 2; ++mi) {
                #pragma unroll
                for (int h = 0; h < 2; ++h) {
                    const int r = mi * 2 + h;
                    #pragma unroll
                    for (int kh = 0; kh < 2; ++kh) {
                        float2 v = make_float2(0.f, 0.f);
                        if (rowok[r]) {
                            v = *(const float2*)(Asrc + (size_t)rows[r] * 128
                                                 + kk + tq * 2 + kh * 8);
                            if (scale) { v.x *= invd[r]; v.y *= invd[r]; }
                        }
                        // reg index: a0:(h0,kh0) a1:(h1,kh0) a2:(h0,kh1) a3:(h1,kh1)
                        split2(v, ah[mi][kh * 2 + h], al[mi][kh * 2 + h]);
                    }
                }
            }

            // ---- MMAs: 3-term hi/lo ----
            #pragma unroll
            for (int mi = 0; mi < 2; ++mi)
                #pragma unroll
                for (int ni = 0; ni < 8; ++ni) {
                    mma16816(acc[mi][ni], ah[mi], bh[ni]);
                    mma16816(acc[mi][ni], al[mi], bh[ni]);
                    mma16816(acc[mi][ni], ah[mi], bl[ni]);
                }
        }
    }

    // ---- epilogue: + c + 1{deg>0} * d ----
    #pragma unroll
    for (int ni = 0; ni < 8; ++ni) {
        const int col = noff + ni * 8 + tq * 2;
        const float2 cc = *(const float2*)(g_c + col);
        const float2 dd = *(const float2*)(g_d + col);
        #pragma unroll
        for (int mi = 0; mi < 2; ++mi) {
            #pragma unroll
            for (int h = 0; h < 2; ++h) {
                const int r = mi * 2 + h;
                if (rowok[r]) {
                    float2 o;
                    o.x = acc[mi][ni][h * 2 + 0] + cc.x + flag[r] * dd.x;
                    o.y = acc[mi][ni][h * 2 + 1] + cc.y + flag[r] * dd.y;
                    *(float2*)(out + (size_t)rows[r] * 128 + col) = o;
                }
            }
        }
    }
}

// ---------------------------------------------------------------------------
// Launch
// ---------------------------------------------------------------------------
extern "C" void kernel_launch(void* const* d_in, const int* in_sizes, int n_in,
                              void* d_out, int out_size) {
    const float* x    = (const float*)d_in[0];
    const void*  eidx = d_in[1];
    const float* W_l1 = (const float*)d_in[2];
    const float* b_l1 = (const float*)d_in[3];
    const float* W_r1 = (const float*)d_in[4];
    const float* W_l2 = (const float*)d_in[5];
    const float* b_l2 = (const float*)d_in[6];
    const float* W_r2 = (const float*)d_in[7];
    float* out = (float*)d_out;

    float *p_deg, *p_agg1, *p_agg2;
    cudaGetSymbolAddress((void**)&p_deg,  g_deg);
    cudaGetSymbolAddress((void**)&p_agg1, g_agg1);
    cudaGetSymbolAddress((void**)&p_agg2, g_agg2);

    // 0) detect index dtype
    detect_idx_kernel<<<1, 32>>>(eidx);

    // 1) zero accumulators
    {
        size_t n4 = (size_t)N_NODES / 4;
        fill0_kernel<<<(unsigned)((n4 + 255) / 256), 256>>>(p_deg, n4);
        n4 = (size_t)N_NODES * 128 / 4;
        fill0_kernel<<<(unsigned)((n4 + 255) / 256), 256>>>(p_agg1, n4);
        fill0_kernel<<<(unsigned)((n4 + 255) / 256), 256>>>(p_agg2, n4);
    }

    // 2) weight pre-products
    weightU_kernel<<<(128 * 384 + 255) / 256, 256>>>(W_l1, W_r1, W_l2, W_r2);
    weightcd_kernel<<<1, 128>>>(b_l1, b_l2, W_l2, W_r2);

    // 3) scatter layer 1 (+ degree)
    {
        long long threads = (long long)N_EDGES * 32;
        scatter1_kernel<<<(unsigned)((threads + 255) / 256), 256>>>(x, eidx);
    }

    // 4) inverse degree
    invdeg_kernel<<<(N_NODES + 255) / 256, 256>>>();

    // 5) scatter layer 2
    {
        long long threads = (long long)N_EDGES * 32;
        scatter2_kernel<<<(unsigned)((threads + 255) / 256), 256>>>(eidx);
    }

    // 6) tensor-core GEMM -> out
    mma_gemm_kernel<<<(N_NODES + 127) / 128, 256>>>(x, out, N_NODES);
}

// round 5
// speedup vs baseline: 1.7143x; 1.0557x over previous
#include <cuda_runtime.h>
#include <cuda_bf16.h>
#include <cstdint>
#include <cstddef>

// Problem constants (match reference)
#define N_NODES 50000
#define N_EDGES 800000
#define D_IN    128
#define D_HID   256
#define D_OUT   128

// ---------------------------------------------------------------------------
// Pipeline:
//   CSR build (histogram -> scan -> permute)      [4B atomics only]
//   gather1: agg1[n] = sum_{src in N(n)} x[src]   [warp/node, no atomics]
//   gather2: agg2[n] = sum m1[src], m1=agg1*invd  [warp/node, no atomics]
//   out = (agg2*invd) @ U1^T + (agg1*invd) @ U2^T + x @ U3^T + c + 1{deg>0} d
//   (single tensor-core GEMM, mma.sync bf16 hi/lo split)
// ---------------------------------------------------------------------------

// Device scratch
__device__ int   g_cnt[N_NODES];          // degree (int)
__device__ int   g_rowoff[N_NODES + 1];   // CSR row offsets
__device__ int   g_cursor[N_NODES];       // fill cursors
__device__ int   g_eadj[N_EDGES];         // CSR adjacency (src per slot)
__device__ float g_invdeg[N_NODES];
__device__ float g_agg1[(size_t)N_NODES * 128];
__device__ float g_agg2[(size_t)N_NODES * 128];
__device__ __nv_bfloat16 g_Uhi[128 * 384];
__device__ __nv_bfloat16 g_Ulo[128 * 384];
__device__ float g_c[128];
__device__ float g_d[128];
__device__ int   g_idx64;

// ---------------------------------------------------------------------------
// mma.sync helpers
// ---------------------------------------------------------------------------
__device__ __forceinline__ void mma16816(float* d, const uint32_t* a, const uint32_t* b) {
    asm volatile(
        "mma.sync.aligned.m16n8k16.row.col.f32.bf16.bf16.f32 "
        "{%0,%1,%2,%3}, {%4,%5,%6,%7}, {%8,%9}, {%0,%1,%2,%3};"
        : "+f"(d[0]), "+f"(d[1]), "+f"(d[2]), "+f"(d[3])
        : "r"(a[0]), "r"(a[1]), "r"(a[2]), "r"(a[3]), "r"(b[0]), "r"(b[1]));
}
__device__ __forceinline__ void split2(float2 v, uint32_t& hi, uint32_t& lo) {
    __nv_bfloat162 h = __float22bfloat162_rn(v);
    float2 hv = __bfloat1622float2(h);
    __nv_bfloat162 l = __float22bfloat162_rn(make_float2(v.x - hv.x, v.y - hv.y));
    hi = *reinterpret_cast<uint32_t*>(&h);
    lo = *reinterpret_cast<uint32_t*>(&l);
}

// ---------------------------------------------------------------------------
// Detect whether edge_index is int64 or int32
// ---------------------------------------------------------------------------
__global__ void detect_idx_kernel(const void* __restrict__ eidx) {
    const long long* p = (const long long*)eidx;
    int lane = threadIdx.x;
    int ok = 1;
    #pragma unroll
    for (int i = 0; i < 16; ++i) {
        long long v = p[lane * 16 + i];
        ok &= (v >= 0 && v < (long long)N_NODES);
    }
    unsigned m = __ballot_sync(0xffffffffu, ok);
    if (lane == 0) g_idx64 = (m == 0xffffffffu) ? 1 : 0;
}

__global__ void zero_cnt_kernel() {
    int i = blockIdx.x * blockDim.x + threadIdx.x;
    if (i < N_NODES) g_cnt[i] = 0;
}

// ---------------------------------------------------------------------------
// CSR build
// ---------------------------------------------------------------------------
__global__ void count_kernel(const void* __restrict__ eidx) {
    int e = blockIdx.x * blockDim.x + threadIdx.x;
    if (e >= N_EDGES) return;
    int dst;
    if (g_idx64) dst = (int)((const long long*)eidx)[N_EDGES + e];
    else         dst = ((const int*)eidx)[N_EDGES + e];
    atomicAdd(&g_cnt[dst], 1);
}

// Single-block exclusive scan over 50000 counts; also writes cursor + invdeg.
#define SCAN_T 1024
#define SCAN_CH 49   // 1024*49 = 50176 >= 50000
__global__ __launch_bounds__(SCAN_T)
void scan_kernel() {
    __shared__ int wsum[32];
    const int t = threadIdx.x;
    const int base = t * SCAN_CH;

    // local sum
    int lsum = 0;
    #pragma unroll 7
    for (int i = 0; i < SCAN_CH; ++i) {
        int idx = base + i;
        if (idx < N_NODES) lsum += g_cnt[idx];
    }

    // warp inclusive scan
    int v = lsum;
    #pragma unroll
    for (int d = 1; d < 32; d <<= 1) {
        int n = __shfl_up_sync(0xffffffffu, v, d);
        if ((t & 31) >= d) v += n;
    }
    if ((t & 31) == 31) wsum[t >> 5] = v;
    __syncthreads();
    if (t < 32) {
        int w = wsum[t];
        #pragma unroll
        for (int d = 1; d < 32; d <<= 1) {
            int n = __shfl_up_sync(0xffffffffu, w, d);
            if (t >= d) w += n;
        }
        wsum[t] = w;
    }
    __syncthreads();
    int myEnd = v + ((t >= 32) ? wsum[(t >> 5) - 1] : 0);
    int myBase = myEnd - lsum;   // exclusive base for this thread's chunk

    // second pass: write offsets / cursor / invdeg
    int run = myBase;
    #pragma unroll 7
    for (int i = 0; i < SCAN_CH; ++i) {
        int idx = base + i;
        if (idx < N_NODES) {
            int c = g_cnt[idx];
            g_rowoff[idx] = run;
            g_cursor[idx] = run;
            g_invdeg[idx] = 1.0f / fmaxf((float)c, 1.0f);
            run += c;
        }
    }
    if (t == SCAN_T - 1) g_rowoff[N_NODES] = N_EDGES;
}

__global__ void fill_csr_kernel(const void* __restrict__ eidx) {
    int e = blockIdx.x * blockDim.x + threadIdx.x;
    if (e >= N_EDGES) return;
    int src, dst;
    if (g_idx64) {
        const long long* ep = (const long long*)eidx;
        src = (int)ep[e]; dst = (int)ep[N_EDGES + e];
    } else {
        const int* ep = (const int*)eidx;
        src = ep[e]; dst = ep[N_EDGES + e];
    }
    int pos = atomicAdd(&g_cursor[dst], 1);
    g_eadj[pos] = src;
}

// ---------------------------------------------------------------------------
// Gather aggregations: one warp per node, lane owns one float4 (128 floats).
// ---------------------------------------------------------------------------
__global__ __launch_bounds__(256)
void gather1_kernel(const float* __restrict__ x) {
    const int warp = (blockIdx.x * blockDim.x + threadIdx.x) >> 5;
    if (warp >= N_NODES) return;
    const int lane = threadIdx.x & 31;
    const int beg = g_rowoff[warp];
    const int end = g_rowoff[warp + 1];
    const float4* x4 = (const float4*)x;

    float4 acc = make_float4(0.f, 0.f, 0.f, 0.f);
    int i = beg;
    for (; i + 2 <= end; i += 2) {
        const int s0 = g_eadj[i];
        const int s1 = g_eadj[i + 1];
        float4 v0 = __ldg(&x4[(size_t)s0 * 32 + lane]);
        float4 v1 = __ldg(&x4[(size_t)s1 * 32 + lane]);
        acc.x += v0.x + v1.x;
        acc.y += v0.y + v1.y;
        acc.z += v0.z + v1.z;
        acc.w += v0.w + v1.w;
    }
    if (i < end) {
        const int s0 = g_eadj[i];
        float4 v0 = __ldg(&x4[(size_t)s0 * 32 + lane]);
        acc.x += v0.x; acc.y += v0.y; acc.z += v0.z; acc.w += v0.w;
    }
    ((float4*)g_agg1)[(size_t)warp * 32 + lane] = acc;
}

__global__ __launch_bounds__(256)
void gather2_kernel() {
    const int warp = (blockIdx.x * blockDim.x + threadIdx.x) >> 5;
    if (warp >= N_NODES) return;
    const int lane = threadIdx.x & 31;
    const int beg = g_rowoff[warp];
    const int end = g_rowoff[warp + 1];
    const float4* a4 = (const float4*)g_agg1;

    float4 acc = make_float4(0.f, 0.f, 0.f, 0.f);
    int i = beg;
    for (; i + 2 <= end; i += 2) {
        const int s0 = g_eadj[i];
        const int s1 = g_eadj[i + 1];
        const float w0 = g_invdeg[s0];
        const float w1 = g_invdeg[s1];
        float4 v0 = __ldg(&a4[(size_t)s0 * 32 + lane]);
        float4 v1 = __ldg(&a4[(size_t)s1 * 32 + lane]);
        acc.x += v0.x * w0 + v1.x * w1;
        acc.y += v0.y * w0 + v1.y * w1;
        acc.z += v0.z * w0 + v1.z * w1;
        acc.w += v0.w * w0 + v1.w * w1;
    }
    if (i < end) {
        const int s0 = g_eadj[i];
        const float w0 = g_invdeg[s0];
        float4 v0 = __ldg(&a4[(size_t)s0 * 32 + lane]);
        acc.x += v0.x * w0; acc.y += v0.y * w0;
        acc.z += v0.z * w0; acc.w += v0.w * w0;
    }
    ((float4*)g_agg2)[(size_t)warp * 32 + lane] = acc;
}

// ---------------------------------------------------------------------------
// Weight pre-products (fp32 compute, bf16 hi/lo output)
// ---------------------------------------------------------------------------
__global__ void weightU_kernel(const float* __restrict__ Wl1,
                               const float* __restrict__ Wr1,
                               const float* __restrict__ Wl2,
                               const float* __restrict__ Wr2) {
    int idx = blockIdx.x * blockDim.x + threadIdx.x;
    if (idx >= 128 * 384) return;
    int a = idx / 384;
    int bcol = idx - a * 384;
    int seg = bcol >> 7;
    int b = bcol & 127;
    float s = 0.f;
    if (seg == 0) {
        #pragma unroll 4
        for (int k = 0; k < 256; ++k) s += Wl2[a * 256 + k] * Wl1[k * 128 + b];
    } else if (seg == 1) {
        #pragma unroll 4
        for (int k = 0; k < 256; ++k)
            s += Wl2[a * 256 + k] * Wr1[k * 128 + b]
               + Wr2[a * 256 + k] * Wl1[k * 128 + b];
    } else {
        #pragma unroll 4
        for (int k = 0; k < 256; ++k) s += Wr2[a * 256 + k] * Wr1[k * 128 + b];
    }
    __nv_bfloat16 hi = __float2bfloat16(s);
    __nv_bfloat16 lo = __float2bfloat16(s - __bfloat162float(hi));
    g_Uhi[idx] = hi;
    g_Ulo[idx] = lo;
}

__global__ void weightcd_kernel(const float* __restrict__ b1,
                                const float* __restrict__ b2,
                                const float* __restrict__ Wl2,
                                const float* __restrict__ Wr2) {
    int a = threadIdx.x;
    if (a < 128) {
        float c = 0.f, d = 0.f;
        #pragma unroll 4
        for (int k = 0; k < 256; ++k) {
            c += Wr2[a * 256 + k] * b1[k];
            d += Wl2[a * 256 + k] * b1[k];
        }
        g_c[a] = b2[a] + c;
        g_d[a] = d;
    }
}

// ---------------------------------------------------------------------------
// Tensor-core GEMM via mma.sync: out[M,128] = A_v[M,384] @ U^T + c + f*d
// A_v: k 0-127 -> agg2*invdeg, 128-255 -> agg1*invdeg, 256-383 -> x.
// ---------------------------------------------------------------------------
__global__ __launch_bounds__(256)
void mma_gemm_kernel(const float* __restrict__ x, float* __restrict__ out, int M) {
    const int tid  = threadIdx.x;
    const int wid  = tid >> 5;
    const int lane = tid & 31;
    const int g    = lane >> 2;
    const int tq   = lane & 3;
    const int m0   = blockIdx.x * 128;
    const int moff = (wid >> 1) * 32;
    const int noff = (wid & 1) * 64;

    int   rows[4];
    bool  rowok[4];
    float invd[4];
    float flag[4];
    #pragma unroll
    for (int r = 0; r < 4; ++r) {
        const int mi = r >> 1, h = r & 1;
        rows[r]  = m0 + moff + mi * 16 + h * 8 + g;
        rowok[r] = rows[r] < M;
        invd[r]  = rowok[r] ? g_invdeg[rows[r]] : 0.f;
        flag[r]  = (rowok[r] && g_cnt[rows[r]] > 0) ? 1.f : 0.f;
    }

    float acc[2][8][4];
    #pragma unroll
    for (int mi = 0; mi < 2; ++mi)
        #pragma unroll
        for (int ni = 0; ni < 8; ++ni)
            #pragma unroll
            for (int q = 0; q < 4; ++q) acc[mi][ni][q] = 0.f;

    #pragma unroll 1
    for (int s = 0; s < 3; ++s) {
        const float* Asrc = (s == 0) ? g_agg2 : ((s == 1) ? g_agg1 : x);
        const bool scale = (s < 2);
        const int kseg = s * 128;

        #pragma unroll 1
        for (int kt = 0; kt < 8; ++kt) {
            const int kk = kt * 16;
            const int kb = kseg + kk;

            uint32_t bh[8][2], bl[8][2];
            #pragma unroll
            for (int ni = 0; ni < 8; ++ni) {
                const int n = noff + ni * 8 + g;
                const size_t base = (size_t)n * 384 + kb + tq * 2;
                bh[ni][0] = *(const uint32_t*)(g_Uhi + base);
                bh[ni][1] = *(const uint32_t*)(g_Uhi + base + 8);
                bl[ni][0] = *(const uint32_t*)(g_Ulo + base);
                bl[ni][1] = *(const uint32_t*)(g_Ulo + base + 8);
            }

            uint32_t ah[2][4], al[2][4];
            #pragma unroll
            for (int mi = 0; mi < 2; ++mi) {
                #pragma unroll
                for (int h = 0; h < 2; ++h) {
                    const int r = mi * 2 + h;
                    #pragma unroll
                    for (int kh = 0; kh < 2; ++kh) {
                        float2 v = make_float2(0.f, 0.f);
                        if (rowok[r]) {
                            v = *(const float2*)(Asrc + (size_t)rows[r] * 128
                                                 + kk + tq * 2 + kh * 8);
                            if (scale) { v.x *= invd[r]; v.y *= invd[r]; }
                        }
                        split2(v, ah[mi][kh * 2 + h], al[mi][kh * 2 + h]);
                    }
                }
            }

            #pragma unroll
            for (int mi = 0; mi < 2; ++mi)
                #pragma unroll
                for (int ni = 0; ni < 8; ++ni) {
                    mma16816(acc[mi][ni], ah[mi], bh[ni]);
                    mma16816(acc[mi][ni], al[mi], bh[ni]);
                    mma16816(acc[mi][ni], ah[mi], bl[ni]);
                }
        }
    }

    #pragma unroll
    for (int ni = 0; ni < 8; ++ni) {
        const int col = noff + ni * 8 + tq * 2;
        const float2 cc = *(const float2*)(g_c + col);
        const float2 dd = *(const float2*)(g_d + col);
        #pragma unroll
        for (int mi = 0; mi < 2; ++mi) {
            #pragma unroll
            for (int h = 0; h < 2; ++h) {
                const int r = mi * 2 + h;
                if (rowok[r]) {
                    float2 o;
                    o.x = acc[mi][ni][h * 2 + 0] + cc.x + flag[r] * dd.x;
                    o.y = acc[mi][ni][h * 2 + 1] + cc.y + flag[r] * dd.y;
                    *(float2*)(out + (size_t)rows[r] * 128 + col) = o;
                }
            }
        }
    }
}

// ---------------------------------------------------------------------------
// Launch
// ---------------------------------------------------------------------------
extern "C" void kernel_launch(void* const* d_in, const int* in_sizes, int n_in,
                              void* d_out, int out_size) {
    const float* x    = (const float*)d_in[0];
    const void*  eidx = d_in[1];
    const float* W_l1 = (const float*)d_in[2];
    const float* b_l1 = (const float*)d_in[3];
    const float* W_r1 = (const float*)d_in[4];
    const float* W_l2 = (const float*)d_in[5];
    const float* b_l2 = (const float*)d_in[6];
    const float* W_r2 = (const float*)d_in[7];
    float* out = (float*)d_out;

    // 0) detect index dtype
    detect_idx_kernel<<<1, 32>>>(eidx);

    // 1) weight pre-products (independent of graph work)
    weightU_kernel<<<(128 * 384 + 255) / 256, 256>>>(W_l1, W_r1, W_l2, W_r2);
    weightcd_kernel<<<1, 128>>>(b_l1, b_l2, W_l2, W_r2);

    // 2) CSR build
    zero_cnt_kernel<<<(N_NODES + 255) / 256, 256>>>();
    count_kernel<<<(N_EDGES + 255) / 256, 256>>>(eidx);
    scan_kernel<<<1, SCAN_T>>>();
    fill_csr_kernel<<<(N_EDGES + 255) / 256, 256>>>(eidx);

    // 3) gather aggregations (warp per node)
    {
        const unsigned blocks = (N_NODES * 32 + 255) / 256;
        gather1_kernel<<<blocks, 256>>>(x);
        gather2_kernel<<<blocks, 256>>>();
    }

    // 4) tensor-core GEMM -> out
    mma_gemm_kernel<<<(N_NODES + 127) / 128, 256>>>(x, out, N_NODES);
}

// round 6
// speedup vs baseline: 1.8160x; 1.0593x over previous
#include <cuda_runtime.h>
#include <cuda_bf16.h>
#include <cstdint>
#include <cstddef>

// Problem constants (match reference)
#define N_NODES 50000
#define N_EDGES 800000
#define D_IN    128
#define D_HID   256
#define D_OUT   128

// ---------------------------------------------------------------------------
// Pipeline (all scaling folded into gather outputs):
//   memset g_cnt
//   count  (inline idx-dtype detect)
//   scan   -> rowoff, cursor, invdeg
//   fill   (inline detect) -> CSR adjacency
//   gather1: m1[n]  = invdeg[n] * sum_{s in N(n)} x[s]
//   gather2: A2[n]  = invdeg[n] * sum_{s in N(n)} m1[s]
//   weights: U packed for mma fragments (bf16 hi/lo), c, d
//   gemm:   out = A2@U1^T + m1@U2^T + x@U3^T + c + 1{deg>0} d   (mma.sync)
// ---------------------------------------------------------------------------

// Device scratch
__device__ int   g_cnt[N_NODES];
__device__ int   g_rowoff[N_NODES + 1];
__device__ int   g_cursor[N_NODES];
__device__ int   g_eadj[N_EDGES];
__device__ float g_invdeg[N_NODES];
__device__ float g_m1[(size_t)N_NODES * 128];   // scaled layer-1 mean
__device__ float g_A2[(size_t)N_NODES * 128];   // scaled layer-2 mean
__device__ uint4 g_Upk[128 * 24 * 4];           // fragment-packed U (hi/lo)
__device__ float g_c[128];
__device__ float g_d[128];

// ---------------------------------------------------------------------------
// mma helpers
// ---------------------------------------------------------------------------
__device__ __forceinline__ void mma16816(float* d, const uint32_t* a, const uint32_t* b) {
    asm volatile(
        "mma.sync.aligned.m16n8k16.row.col.f32.bf16.bf16.f32 "
        "{%0,%1,%2,%3}, {%4,%5,%6,%7}, {%8,%9}, {%0,%1,%2,%3};"
        : "+f"(d[0]), "+f"(d[1]), "+f"(d[2]), "+f"(d[3])
        : "r"(a[0]), "r"(a[1]), "r"(a[2]), "r"(a[3]), "r"(b[0]), "r"(b[1]));
}
__device__ __forceinline__ void split2(float2 v, uint32_t& hi, uint32_t& lo) {
    __nv_bfloat162 h = __float22bfloat162_rn(v);
    float2 hv = __bfloat1622float2(h);
    __nv_bfloat162 l = __float22bfloat162_rn(make_float2(v.x - hv.x, v.y - hv.y));
    hi = *reinterpret_cast<uint32_t*>(&h);
    lo = *reinterpret_cast<uint32_t*>(&l);
}
__device__ __forceinline__ uint32_t packbf2(float a, float b) {
    __nv_bfloat162 h = __float22bfloat162_rn(make_float2(a, b));
    return *reinterpret_cast<uint32_t*>(&h);
}

// Per-block idx-dtype detection: int32 data read as int64 packs two values in
// [0,50000) into one word -> >= 2^32 almost surely. All blocks agree.
__device__ __forceinline__ int detect_idx64_block(const void* eidx) {
    __shared__ int s_idx64;
    if (threadIdx.x < 32) {
        const long long* p = (const long long*)eidx;
        int ok = 1;
        #pragma unroll
        for (int i = 0; i < 16; ++i) {
            long long v = p[threadIdx.x * 16 + i];
            ok &= (v >= 0 && v < (long long)N_NODES);
        }
        unsigned m = __ballot_sync(0xffffffffu, ok);
        if (threadIdx.x == 0) s_idx64 = (m == 0xffffffffu) ? 1 : 0;
    }
    __syncthreads();
    return s_idx64;
}

// ---------------------------------------------------------------------------
// CSR build
// ---------------------------------------------------------------------------
__global__ void count_kernel(const void* __restrict__ eidx) {
    const int idx64 = detect_idx64_block(eidx);
    int e = blockIdx.x * blockDim.x + threadIdx.x;
    if (e >= N_EDGES) return;
    int dst;
    if (idx64) dst = (int)((const long long*)eidx)[N_EDGES + e];
    else       dst = ((const int*)eidx)[N_EDGES + e];
    atomicAdd(&g_cnt[dst], 1);
}

#define SCAN_T 1024
#define SCAN_CH 49   // 1024*49 = 50176 >= 50000
__global__ __launch_bounds__(SCAN_T)
void scan_kernel() {
    __shared__ int wsum[32];
    const int t = threadIdx.x;
    const int base = t * SCAN_CH;

    int lsum = 0;
    #pragma unroll 7
    for (int i = 0; i < SCAN_CH; ++i) {
        int idx = base + i;
        if (idx < N_NODES) lsum += g_cnt[idx];
    }

    int v = lsum;
    #pragma unroll
    for (int d = 1; d < 32; d <<= 1) {
        int n = __shfl_up_sync(0xffffffffu, v, d);
        if ((t & 31) >= d) v += n;
    }
    if ((t & 31) == 31) wsum[t >> 5] = v;
    __syncthreads();
    if (t < 32) {
        int w = wsum[t];
        #pragma unroll
        for (int d = 1; d < 32; d <<= 1) {
            int n = __shfl_up_sync(0xffffffffu, w, d);
            if (t >= d) w += n;
        }
        wsum[t] = w;
    }
    __syncthreads();
    int myEnd = v + ((t >= 32) ? wsum[(t >> 5) - 1] : 0);
    int run = myEnd - lsum;

    #pragma unroll 7
    for (int i = 0; i < SCAN_CH; ++i) {
        int idx = base + i;
        if (idx < N_NODES) {
            int c = g_cnt[idx];
            g_rowoff[idx] = run;
            g_cursor[idx] = run;
            g_invdeg[idx] = 1.0f / fmaxf((float)c, 1.0f);
            run += c;
        }
    }
    if (t == SCAN_T - 1) g_rowoff[N_NODES] = N_EDGES;
}

__global__ void fill_csr_kernel(const void* __restrict__ eidx) {
    const int idx64 = detect_idx64_block(eidx);
    int e = blockIdx.x * blockDim.x + threadIdx.x;
    if (e >= N_EDGES) return;
    int src, dst;
    if (idx64) {
        const long long* ep = (const long long*)eidx;
        src = (int)ep[e]; dst = (int)ep[N_EDGES + e];
    } else {
        const int* ep = (const int*)eidx;
        src = ep[e]; dst = ep[N_EDGES + e];
    }
    int pos = atomicAdd(&g_cursor[dst], 1);
    g_eadj[pos] = src;
}

// ---------------------------------------------------------------------------
// Gathers: one warp per node, lane owns one float4 (128 floats), unroll 4.
// ---------------------------------------------------------------------------
template<bool FIRST>
__global__ __launch_bounds__(256)
void gather_kernel(const float* __restrict__ src_feat, float* __restrict__ dst_feat) {
    const int node = (blockIdx.x * blockDim.x + threadIdx.x) >> 5;
    if (node >= N_NODES) return;
    const int lane = threadIdx.x & 31;
    const int beg = g_rowoff[node];
    const int end = g_rowoff[node + 1];
    const float4* f4 = (const float4*)src_feat;

    float4 acc = make_float4(0.f, 0.f, 0.f, 0.f);
    int i = beg;
    for (; i + 4 <= end; i += 4) {
        const int s0 = g_eadj[i];
        const int s1 = g_eadj[i + 1];
        const int s2 = g_eadj[i + 2];
        const int s3 = g_eadj[i + 3];
        float4 v0 = __ldg(&f4[(size_t)s0 * 32 + lane]);
        float4 v1 = __ldg(&f4[(size_t)s1 * 32 + lane]);
        float4 v2 = __ldg(&f4[(size_t)s2 * 32 + lane]);
        float4 v3 = __ldg(&f4[(size_t)s3 * 32 + lane]);
        acc.x += (v0.x + v1.x) + (v2.x + v3.x);
        acc.y += (v0.y + v1.y) + (v2.y + v3.y);
        acc.z += (v0.z + v1.z) + (v2.z + v3.z);
        acc.w += (v0.w + v1.w) + (v2.w + v3.w);
    }
    for (; i < end; ++i) {
        const int s0 = g_eadj[i];
        float4 v0 = __ldg(&f4[(size_t)s0 * 32 + lane]);
        acc.x += v0.x; acc.y += v0.y; acc.z += v0.z; acc.w += v0.w;
    }
    const float w = g_invdeg[node];
    acc.x *= w; acc.y *= w; acc.z *= w; acc.w *= w;
    ((float4*)dst_feat)[(size_t)node * 32 + lane] = acc;
}

// ---------------------------------------------------------------------------
// Weights: U fragment-packed (hi/lo) + c, d.
// Upk[((n*24)+ktg)*4+tq] = {hi(k0,k0+1), hi(k2,k2+1), lo(k0,k0+1), lo(k2,k2+1)}
// with ktg = 0..23 (global k16-tile), k0 = (ktg%8)*16 + 2*tq, k2 = k0 + 8,
// seg = ktg/8 selects U1/U2/U3.
// ---------------------------------------------------------------------------
__global__ __launch_bounds__(256)
void weight_kernel(const float* __restrict__ Wl1,
                   const float* __restrict__ Wr1,
                   const float* __restrict__ Wl2,
                   const float* __restrict__ Wr2,
                   const float* __restrict__ b1,
                   const float* __restrict__ b2) {
    const int tid = blockIdx.x * blockDim.x + threadIdx.x;

    if (tid < 128 * 96) {
        const int n   = tid / 96;
        const int rem = tid - n * 96;
        const int ktg = rem >> 2;
        const int tq  = rem & 3;
        const int seg = ktg >> 3;
        const int kb  = (ktg & 7) * 16;
        const int k0  = kb + 2 * tq;

        float u[4] = {0.f, 0.f, 0.f, 0.f};   // k0, k0+1, k0+8, k0+9
        const float* A1 = Wl2 + (size_t)n * 256;
        const float* A2 = Wr2 + (size_t)n * 256;
        #pragma unroll 4
        for (int t = 0; t < 256; ++t) {
            const float wl2 = A1[t];
            const float wr2 = A2[t];
            const float* rl = Wl1 + (size_t)t * 128 + k0;
            const float* rr = Wr1 + (size_t)t * 128 + k0;
            if (seg == 0) {
                u[0] += wl2 * rl[0]; u[1] += wl2 * rl[1];
                u[2] += wl2 * rl[8]; u[3] += wl2 * rl[9];
            } else if (seg == 1) {
                u[0] += wl2 * rr[0] + wr2 * rl[0];
                u[1] += wl2 * rr[1] + wr2 * rl[1];
                u[2] += wl2 * rr[8] + wr2 * rl[8];
                u[3] += wl2 * rr[9] + wr2 * rl[9];
            } else {
                u[0] += wr2 * rr[0]; u[1] += wr2 * rr[1];
                u[2] += wr2 * rr[8]; u[3] += wr2 * rr[9];
            }
        }
        uint32_t h0 = packbf2(u[0], u[1]);
        uint32_t h1 = packbf2(u[2], u[3]);
        float r0 = u[0] - __bfloat162float(__ushort_as_bfloat16((uint16_t)(h0 & 0xffff)));
        float r1 = u[1] - __bfloat162float(__ushort_as_bfloat16((uint16_t)(h0 >> 16)));
        float r2 = u[2] - __bfloat162float(__ushort_as_bfloat16((uint16_t)(h1 & 0xffff)));
        float r3 = u[3] - __bfloat162float(__ushort_as_bfloat16((uint16_t)(h1 >> 16)));
        uint32_t l0 = packbf2(r0, r1);
        uint32_t l1 = packbf2(r2, r3);
        g_Upk[tid] = make_uint4(h0, h1, l0, l1);
    } else if (tid < 128 * 96 + 128) {
        const int a = tid - 128 * 96;
        float c = 0.f, d = 0.f;
        #pragma unroll 4
        for (int k = 0; k < 256; ++k) {
            c += Wr2[a * 256 + k] * b1[k];
            d += Wl2[a * 256 + k] * b1[k];
        }
        g_c[a] = b2[a] + c;
        g_d[a] = d;
    }
}

// ---------------------------------------------------------------------------
// Tensor-core GEMM: out[M,128] = [A2 | m1 | x] @ U^T + c + 1{deg>0} d
// CTA 128x128, 8 warps 4x2; warp 32x64 = 2x8 m16n8k16 fragments.
// ---------------------------------------------------------------------------
__global__ __launch_bounds__(256)
void mma_gemm_kernel(const float* __restrict__ x, float* __restrict__ out, int M) {
    const int tid  = threadIdx.x;
    const int wid  = tid >> 5;
    const int lane = tid & 31;
    const int g    = lane >> 2;
    const int tq   = lane & 3;
    const int m0   = blockIdx.x * 128;
    const int moff = (wid >> 1) * 32;
    const int noff = (wid & 1) * 64;

    int   rows[4];
    bool  rowok[4];
    float flag[4];
    #pragma unroll
    for (int r = 0; r < 4; ++r) {
        const int mi = r >> 1, h = r & 1;
        rows[r]  = m0 + moff + mi * 16 + h * 8 + g;
        rowok[r] = rows[r] < M;
        flag[r]  = (rowok[r] && g_cnt[rows[r]] > 0) ? 1.f : 0.f;
    }

    float acc[2][8][4];
    #pragma unroll
    for (int mi = 0; mi < 2; ++mi)
        #pragma unroll
        for (int ni = 0; ni < 8; ++ni)
            #pragma unroll
            for (int q = 0; q < 4; ++q) acc[mi][ni][q] = 0.f;

    #pragma unroll 1
    for (int s = 0; s < 3; ++s) {
        const float* Asrc = (s == 0) ? g_A2 : ((s == 1) ? g_m1 : x);

        #pragma unroll 1
        for (int kt = 0; kt < 8; ++kt) {
            const int kk  = kt * 16;
            const int ktg = s * 8 + kt;

            // B fragments: one uint4 per ni = {bh0, bh1, bl0, bl1}
            uint4 bf[8];
            #pragma unroll
            for (int ni = 0; ni < 8; ++ni) {
                const int n = noff + ni * 8 + g;
                bf[ni] = g_Upk[(n * 24 + ktg) * 4 + tq];
            }

            // A fragments (load fp32, split hi/lo)
            uint32_t ah[2][4], al[2][4];
            #pragma unroll
            for (int mi = 0; mi < 2; ++mi) {
                #pragma unroll
                for (int h = 0; h < 2; ++h) {
                    const int r = mi * 2 + h;
                    #pragma unroll
                    for (int kh = 0; kh < 2; ++kh) {
                        float2 v = make_float2(0.f, 0.f);
                        if (rowok[r])
                            v = *(const float2*)(Asrc + (size_t)rows[r] * 128
                                                 + kk + tq * 2 + kh * 8);
                        split2(v, ah[mi][kh * 2 + h], al[mi][kh * 2 + h]);
                    }
                }
            }

            #pragma unroll
            for (int mi = 0; mi < 2; ++mi)
                #pragma unroll
                for (int ni = 0; ni < 8; ++ni) {
                    uint32_t bh[2] = {bf[ni].x, bf[ni].y};
                    uint32_t bl[2] = {bf[ni].z, bf[ni].w};
                    mma16816(acc[mi][ni], ah[mi], bh);
                    mma16816(acc[mi][ni], al[mi], bh);
                    mma16816(acc[mi][ni], ah[mi], bl);
                }
        }
    }

    #pragma unroll
    for (int ni = 0; ni < 8; ++ni) {
        const int col = noff + ni * 8 + tq * 2;
        const float2 cc = *(const float2*)(g_c + col);
        const float2 dd = *(const float2*)(g_d + col);
        #pragma unroll
        for (int mi = 0; mi < 2; ++mi) {
            #pragma unroll
            for (int h = 0; h < 2; ++h) {
                const int r = mi * 2 + h;
                if (rowok[r]) {
                    float2 o;
                    o.x = acc[mi][ni][h * 2 + 0] + cc.x + flag[r] * dd.x;
                    o.y = acc[mi][ni][h * 2 + 1] + cc.y + flag[r] * dd.y;
                    *(float2*)(out + (size_t)rows[r] * 128 + col) = o;
                }
            }
        }
    }
}

// ---------------------------------------------------------------------------
// Launch
// ---------------------------------------------------------------------------
extern "C" void kernel_launch(void* const* d_in, const int* in_sizes, int n_in,
                              void* d_out, int out_size) {
    const float* x    = (const float*)d_in[0];
    const void*  eidx = d_in[1];
    const float* W_l1 = (const float*)d_in[2];
    const float* b_l1 = (const float*)d_in[3];
    const float* W_r1 = (const float*)d_in[4];
    const float* W_l2 = (const float*)d_in[5];
    const float* b_l2 = (const float*)d_in[6];
    const float* W_r2 = (const float*)d_in[7];
    float* out = (float*)d_out;

    float *p_m1, *p_A2;
    int *p_cnt;
    cudaGetSymbolAddress((void**)&p_cnt, g_cnt);
    cudaGetSymbolAddress((void**)&p_m1,  g_m1);
    cudaGetSymbolAddress((void**)&p_A2,  g_A2);

    // memset node (graph-capturable, not an allocation)
    cudaMemsetAsync(p_cnt, 0, (size_t)N_NODES * sizeof(int));

    // CSR build (inline dtype detection)
    count_kernel<<<(N_EDGES + 255) / 256, 256>>>(eidx);
    scan_kernel<<<1, SCAN_T>>>();
    fill_csr_kernel<<<(N_EDGES + 255) / 256, 256>>>(eidx);

    // gathers (warp per node)
    const unsigned gblocks = (N_NODES * 32 + 255) / 256;
    gather_kernel<true><<<gblocks, 256>>>(x, p_m1);
    gather_kernel<false><<<gblocks, 256>>>(p_m1, p_A2);

    // weights (packed) + bias terms
    weight_kernel<<<(128 * 96 + 128 + 255) / 256, 256>>>(W_l1, W_r1, W_l2, W_r2, b_l1, b_l2);

    // fused tensor-core GEMM
    mma_gemm_kernel<<<(N_NODES + 127) / 128, 256>>>(x, out, N_NODES);
}